// round 1
// baseline (speedup 1.0000x reference)
#include <cuda_runtime.h>
#include <cstdint>
#include <math.h>

// ---------------- problem constants ----------------
#define B_   4
#define S_   2048
#define H_   1024
#define NH_  16
#define HD_  64
#define FF_  4096
#define MR_  (B_*S_)        // 8192 rows

// ---------------- scratch (device globals; no runtime allocation) ----------------
__device__ float g_q  [(size_t)MR_*H_];
__device__ float g_k  [(size_t)MR_*H_];
__device__ float g_v  [(size_t)MR_*H_];
__device__ float g_ctx[(size_t)MR_*H_];
__device__ float g_tmp[(size_t)MR_*H_];
__device__ float g_x1 [(size_t)MR_*H_];
__device__ float g_ff [(size_t)MR_*FF_];

// ---------------- helpers ----------------
__device__ __forceinline__ uint32_t f2tf(float f) {
    uint32_t u;
    asm("cvt.rna.tf32.f32 %0, %1;" : "=r"(u) : "f"(f));
    return u;
}

__device__ __forceinline__ void mma8(float* c, const uint32_t* a, const uint32_t* b) {
    asm volatile(
        "mma.sync.aligned.m16n8k8.row.col.f32.tf32.tf32.f32 "
        "{%0,%1,%2,%3}, {%4,%5,%6,%7}, {%8,%9}, {%0,%1,%2,%3};"
        : "+f"(c[0]), "+f"(c[1]), "+f"(c[2]), "+f"(c[3])
        : "r"(a[0]), "r"(a[1]), "r"(a[2]), "r"(a[3]), "r"(b[0]), "r"(b[1]));
}

// ---------------- epilogues ----------------
struct EpiQKV {   // write [B,NH,S,HD] layout, add bias
    const float* bias; float* dst;
    __device__ __forceinline__ void operator()(int r, int c, float v) const {
        int b = r >> 11, s = r & 2047, h = c >> 6, d = c & 63;
        dst[(((size_t)(b*NH_ + h))*S_ + s)*HD_ + d] = v + bias[c];
    }
};
struct EpiBiasRes {   // out = v + bias + residual   (N = H_)
    const float* bias; const float* res; float* dst;
    __device__ __forceinline__ void operator()(int r, int c, float v) const {
        size_t idx = (size_t)r*H_ + c;
        dst[idx] = v + bias[c] + res[idx];
    }
};
struct EpiGelu {      // out = gelu_tanh(v + bias)   (N = FF_)
    const float* bias; float* dst;
    __device__ __forceinline__ void operator()(int r, int c, float v) const {
        float x = v + bias[c];
        float t = tanhf(0.7978845608028654f * (x + 0.044715f * x * x * x));
        dst[(size_t)r*FF_ + c] = 0.5f * x * (1.0f + t);
    }
};

// ---------------- tf32 GEMM: C[M,N] = A[M,K] @ B[K,N], epilogue functor ----------------
// block tile 128x128x16, 256 threads = 8 warps in 2x4 grid, warp tile 64x32
template <class Epi>
__global__ __launch_bounds__(256, 2) void gemm_tf32(
    const float* __restrict__ A, const float* __restrict__ Bm,
    int M, int N, int K, Epi epi)
{
    __shared__ uint32_t As[16][132];   // [k][m], tf32 bits
    __shared__ uint32_t Bs[16][132];   // [k][n], tf32 bits

    const int tid  = threadIdx.x;
    const int w    = tid >> 5, lane = tid & 31;
    const int grp  = lane >> 2, tig = lane & 3;
    const int warpM = w >> 2, warpN = w & 3;       // 2 x 4
    const int row0 = blockIdx.y * 128, col0 = blockIdx.x * 128;

    float c[4][4][4];
    #pragma unroll
    for (int i = 0; i < 4; i++)
        #pragma unroll
        for (int j = 0; j < 4; j++)
            #pragma unroll
            for (int l = 0; l < 4; l++) c[i][j][l] = 0.f;

    for (int kk = 0; kk < K; kk += 16) {
        // A tile: transpose into As[k][m]
        #pragma unroll
        for (int i = 0; i < 2; i++) {
            int pos = tid + i*256;                 // 0..511 float4 slots
            int m = pos >> 2, k4 = (pos & 3) << 2;
            float4 v = *reinterpret_cast<const float4*>(A + (size_t)(row0 + m)*K + kk + k4);
            As[k4+0][m] = f2tf(v.x); As[k4+1][m] = f2tf(v.y);
            As[k4+2][m] = f2tf(v.z); As[k4+3][m] = f2tf(v.w);
        }
        // B tile: direct into Bs[k][n]
        #pragma unroll
        for (int i = 0; i < 2; i++) {
            int pos = tid + i*256;
            int k = pos >> 5, n4 = (pos & 31) << 2;
            float4 v = *reinterpret_cast<const float4*>(Bm + (size_t)(kk + k)*N + col0 + n4);
            Bs[k][n4+0] = f2tf(v.x); Bs[k][n4+1] = f2tf(v.y);
            Bs[k][n4+2] = f2tf(v.z); Bs[k][n4+3] = f2tf(v.w);
        }
        __syncthreads();

        #pragma unroll
        for (int ks = 0; ks < 16; ks += 8) {
            uint32_t a[4][4], b[4][2];
            #pragma unroll
            for (int mt = 0; mt < 4; mt++) {
                int rb = warpM*64 + mt*16 + grp;
                a[mt][0] = As[ks+tig  ][rb];   a[mt][1] = As[ks+tig  ][rb+8];
                a[mt][2] = As[ks+tig+4][rb];   a[mt][3] = As[ks+tig+4][rb+8];
            }
            #pragma unroll
            for (int nt = 0; nt < 4; nt++) {
                int cb = warpN*32 + nt*8 + grp;
                b[nt][0] = Bs[ks+tig][cb];     b[nt][1] = Bs[ks+tig+4][cb];
            }
            #pragma unroll
            for (int mt = 0; mt < 4; mt++)
                #pragma unroll
                for (int nt = 0; nt < 4; nt++)
                    mma8(c[mt][nt], a[mt], b[nt]);
        }
        __syncthreads();
    }

    #pragma unroll
    for (int mt = 0; mt < 4; mt++) {
        int r = row0 + warpM*64 + mt*16 + grp;
        #pragma unroll
        for (int nt = 0; nt < 4; nt++) {
            int cc = col0 + warpN*32 + nt*8 + tig*2;
            epi(r,     cc,   c[mt][nt][0]);
            epi(r,     cc+1, c[mt][nt][1]);
            epi(r+8,   cc,   c[mt][nt][2]);
            epi(r+8,   cc+1, c[mt][nt][3]);
        }
    }
}

// ---------------- flash attention: 64-query tile / block, stream 64-key tiles ----------------
// grid = (S/64, B*NH), 256 threads = 8 warps (2x4)
__global__ __launch_bounds__(256) void attn_kernel(const float* __restrict__ mask)
{
    extern __shared__ char smem_raw[];
    const int TPITCH = 68;                 // 64 + 4 pad
    uint32_t (*Qs)[68] = (uint32_t(*)[68])(smem_raw);               // [d][q]
    uint32_t (*Ks)[68] = (uint32_t(*)[68])(smem_raw + 17408);       // [d][key]
    uint32_t (*Vs)[68] = (uint32_t(*)[68])(smem_raw + 2*17408);     // [key][d]
    float    (*Ss)[68] = (float   (*)[68])(smem_raw + 3*17408);     // [q][key]
    float* m_s   = (float*)(smem_raw + 4*17408);
    float* l_s   = m_s + 64;
    float* al_s  = l_s + 64;
    float* msk_s = al_s + 64;
    (void)TPITCH;

    const int tid = threadIdx.x, w = tid >> 5, lane = tid & 31;
    const int grp = lane >> 2, tig = lane & 3;
    const int warpM = w >> 2, warpN = w & 3;       // rows 2x32, cols 4x16
    const int qt = blockIdx.x, bh = blockIdx.y;
    const int b = bh >> 4, h = bh & 15;

    const float* qg = g_q + (size_t)bh * S_ * HD_;
    const float* kg = g_k + (size_t)bh * S_ * HD_;
    const float* vg = g_v + (size_t)bh * S_ * HD_;

    // load Q tile transposed: Qs[d][i]
    #pragma unroll
    for (int i = 0; i < 4; i++) {
        int pos = tid + i*256;              // 1024 float4 slots
        int qr = pos >> 4, d4 = (pos & 15) << 2;
        float4 v = *reinterpret_cast<const float4*>(qg + (size_t)(qt*64 + qr)*HD_ + d4);
        Qs[d4+0][qr] = f2tf(v.x); Qs[d4+1][qr] = f2tf(v.y);
        Qs[d4+2][qr] = f2tf(v.z); Qs[d4+3][qr] = f2tf(v.w);
    }
    if (tid < 64) { m_s[tid] = -1e30f; l_s[tid] = 0.f; }

    float o[2][2][4];
    #pragma unroll
    for (int i = 0; i < 2; i++)
        #pragma unroll
        for (int j = 0; j < 2; j++)
            #pragma unroll
            for (int l = 0; l < 4; l++) o[i][j][l] = 0.f;

    const float scale = 0.125f;   // 1/sqrt(64)

    for (int kt = 0; kt < S_/64; kt++) {
        __syncthreads();   // prev iter's smem reads done; Q load visible on iter 0

        // load K (transposed) and V (direct) tiles + mask slice
        #pragma unroll
        for (int i = 0; i < 4; i++) {
            int pos = tid + i*256;
            int r = pos >> 4, d4 = (pos & 15) << 2;
            float4 kv = *reinterpret_cast<const float4*>(kg + (size_t)(kt*64 + r)*HD_ + d4);
            Ks[d4+0][r] = f2tf(kv.x); Ks[d4+1][r] = f2tf(kv.y);
            Ks[d4+2][r] = f2tf(kv.z); Ks[d4+3][r] = f2tf(kv.w);
            float4 vv = *reinterpret_cast<const float4*>(vg + (size_t)(kt*64 + r)*HD_ + d4);
            Vs[r][d4+0] = f2tf(vv.x); Vs[r][d4+1] = f2tf(vv.y);
            Vs[r][d4+2] = f2tf(vv.z); Vs[r][d4+3] = f2tf(vv.w);
        }
        if (tid < 64) msk_s[tid] = mask[(size_t)b*S_ + kt*64 + tid];
        __syncthreads();

        // scores = Q @ K^T  (raw dot products in frags)
        float sc[2][2][4];
        #pragma unroll
        for (int i = 0; i < 2; i++)
            #pragma unroll
            for (int j = 0; j < 2; j++)
                #pragma unroll
                for (int l = 0; l < 4; l++) sc[i][j][l] = 0.f;

        #pragma unroll
        for (int ks = 0; ks < 64; ks += 8) {
            uint32_t a[2][4], bb[2][2];
            #pragma unroll
            for (int mt = 0; mt < 2; mt++) {
                int rb = warpM*32 + mt*16 + grp;
                a[mt][0] = Qs[ks+tig  ][rb];  a[mt][1] = Qs[ks+tig  ][rb+8];
                a[mt][2] = Qs[ks+tig+4][rb];  a[mt][3] = Qs[ks+tig+4][rb+8];
            }
            #pragma unroll
            for (int nt = 0; nt < 2; nt++) {
                int cb = warpN*16 + nt*8 + grp;
                bb[nt][0] = Ks[ks+tig][cb];   bb[nt][1] = Ks[ks+tig+4][cb];
            }
            #pragma unroll
            for (int mt = 0; mt < 2; mt++)
                #pragma unroll
                for (int nt = 0; nt < 2; nt++)
                    mma8(sc[mt][nt], a[mt], bb[nt]);
        }
        // spill scores to smem
        #pragma unroll
        for (int mt = 0; mt < 2; mt++) {
            int r = warpM*32 + mt*16 + grp;
            #pragma unroll
            for (int nt = 0; nt < 2; nt++) {
                int cc = warpN*16 + nt*8 + tig*2;
                Ss[r  ][cc] = sc[mt][nt][0];  Ss[r  ][cc+1] = sc[mt][nt][1];
                Ss[r+8][cc] = sc[mt][nt][2];  Ss[r+8][cc+1] = sc[mt][nt][3];
            }
        }
        __syncthreads();

        // online softmax: one thread per query row
        if (tid < 64) {
            int row = tid;
            float mold = m_s[row], mnew = mold;
            for (int j = 0; j < 64; j++) {
                float v = Ss[row][j]*scale + msk_s[j];
                mnew = fmaxf(mnew, v);
            }
            float alpha = __expf(mold - mnew);
            float lsum = 0.f;
            for (int j = 0; j < 64; j++) {
                float p = __expf(Ss[row][j]*scale + msk_s[j] - mnew);
                lsum += p;
                Ss[row][j] = __uint_as_float(f2tf(p));   // tf32 bits for PV mma
            }
            m_s[row]  = mnew;
            l_s[row]  = l_s[row]*alpha + lsum;
            al_s[row] = alpha;
        }
        __syncthreads();

        // rescale O accumulator
        #pragma unroll
        for (int mt = 0; mt < 2; mt++) {
            int rb = warpM*32 + mt*16 + grp;
            float a0 = al_s[rb], a1 = al_s[rb+8];
            #pragma unroll
            for (int nt = 0; nt < 2; nt++) {
                o[mt][nt][0] *= a0; o[mt][nt][1] *= a0;
                o[mt][nt][2] *= a1; o[mt][nt][3] *= a1;
            }
        }
        // O += P @ V
        #pragma unroll
        for (int ks = 0; ks < 64; ks += 8) {
            uint32_t a[2][4], bb[2][2];
            #pragma unroll
            for (int mt = 0; mt < 2; mt++) {
                int rb = warpM*32 + mt*16 + grp;
                a[mt][0] = __float_as_uint(Ss[rb  ][ks+tig  ]);
                a[mt][1] = __float_as_uint(Ss[rb+8][ks+tig  ]);
                a[mt][2] = __float_as_uint(Ss[rb  ][ks+tig+4]);
                a[mt][3] = __float_as_uint(Ss[rb+8][ks+tig+4]);
            }
            #pragma unroll
            for (int nt = 0; nt < 2; nt++) {
                int cb = warpN*16 + nt*8 + grp;
                bb[nt][0] = Vs[ks+tig][cb];  bb[nt][1] = Vs[ks+tig+4][cb];
            }
            #pragma unroll
            for (int mt = 0; mt < 2; mt++)
                #pragma unroll
                for (int nt = 0; nt < 2; nt++)
                    mma8(o[mt][nt], a[mt], bb[nt]);
        }
    }

    // final: O / l, write ctx in [B,S,H] layout
    #pragma unroll
    for (int mt = 0; mt < 2; mt++) {
        int rb = warpM*32 + mt*16 + grp;
        float inv0 = 1.f / l_s[rb], inv1 = 1.f / l_s[rb+8];
        int q = qt*64 + rb;
        #pragma unroll
        for (int nt = 0; nt < 2; nt++) {
            int dcol = warpN*16 + nt*8 + tig*2;
            size_t base = ((size_t)(b*S_ + q))*H_ + h*HD_ + dcol;
            g_ctx[base]            = o[mt][nt][0]*inv0;
            g_ctx[base+1]          = o[mt][nt][1]*inv0;
            g_ctx[base + 8*(size_t)H_]     = o[mt][nt][2]*inv1;
            g_ctx[base + 8*(size_t)H_ + 1] = o[mt][nt][3]*inv1;
        }
    }
}

// ---------------- layernorm: one block per row (H=1024, 256 threads, float4) ----------------
__global__ __launch_bounds__(256) void ln_kernel(
    const float* __restrict__ in, const float* __restrict__ g,
    const float* __restrict__ bb, float* __restrict__ out)
{
    __shared__ float red[18];
    const int row = blockIdx.x, tid = threadIdx.x;
    const float4 x = reinterpret_cast<const float4*>(in + (size_t)row*H_)[tid];
    float s  = x.x + x.y + x.z + x.w;
    float sq = x.x*x.x + x.y*x.y + x.z*x.z + x.w*x.w;
    #pragma unroll
    for (int off = 16; off > 0; off >>= 1) {
        s  += __shfl_xor_sync(0xffffffffu, s,  off);
        sq += __shfl_xor_sync(0xffffffffu, sq, off);
    }
    if ((tid & 31) == 0) { red[tid>>5] = s; red[8 + (tid>>5)] = sq; }
    __syncthreads();
    if (tid == 0) {
        float a = 0.f, c2 = 0.f;
        #pragma unroll
        for (int i = 0; i < 8; i++) { a += red[i]; c2 += red[8+i]; }
        red[16] = a; red[17] = c2;
    }
    __syncthreads();
    float mu  = red[16] * (1.f/1024.f);
    float var = red[17] * (1.f/1024.f) - mu*mu;
    float inv = rsqrtf(var + 1e-12f);
    float4 gv = reinterpret_cast<const float4*>(g)[tid];
    float4 bv = reinterpret_cast<const float4*>(bb)[tid];
    float4 o4;
    o4.x = (x.x - mu)*inv*gv.x + bv.x;
    o4.y = (x.y - mu)*inv*gv.y + bv.y;
    o4.z = (x.z - mu)*inv*gv.z + bv.z;
    o4.w = (x.w - mu)*inv*gv.w + bv.w;
    reinterpret_cast<float4*>(out + (size_t)row*H_)[tid] = o4;
}

// ---------------- launch ----------------
extern "C" void kernel_launch(void* const* d_in, const int* in_sizes, int n_in,
                              void* d_out, int out_size)
{
    (void)in_sizes; (void)n_in; (void)out_size;
    const float* x    = (const float*)d_in[0];
    const float* mask = (const float*)d_in[1];
    const float* Wq   = (const float*)d_in[2];
    const float* bq   = (const float*)d_in[3];
    const float* Wk   = (const float*)d_in[4];
    const float* bk   = (const float*)d_in[5];
    const float* Wv   = (const float*)d_in[6];
    const float* bv   = (const float*)d_in[7];
    const float* Wo   = (const float*)d_in[8];
    const float* bo   = (const float*)d_in[9];
    const float* ln1g = (const float*)d_in[10];
    const float* ln1b = (const float*)d_in[11];
    const float* W1   = (const float*)d_in[12];
    const float* b1   = (const float*)d_in[13];
    const float* W2   = (const float*)d_in[14];
    const float* b2   = (const float*)d_in[15];
    const float* ln2g = (const float*)d_in[16];
    const float* ln2b = (const float*)d_in[17];
    float* out = (float*)d_out;

    float *qp, *kp, *vp, *ctxp, *tmpp, *x1p, *ffp;
    cudaGetSymbolAddress((void**)&qp,   g_q);
    cudaGetSymbolAddress((void**)&kp,   g_k);
    cudaGetSymbolAddress((void**)&vp,   g_v);
    cudaGetSymbolAddress((void**)&ctxp, g_ctx);
    cudaGetSymbolAddress((void**)&tmpp, g_tmp);
    cudaGetSymbolAddress((void**)&x1p,  g_x1);
    cudaGetSymbolAddress((void**)&ffp,  g_ff);

    dim3 blk(256);

    // QKV projections
    gemm_tf32<<<dim3(H_/128, MR_/128), blk>>>(x, Wq, MR_, H_, H_, EpiQKV{bq, qp});
    gemm_tf32<<<dim3(H_/128, MR_/128), blk>>>(x, Wk, MR_, H_, H_, EpiQKV{bk, kp});
    gemm_tf32<<<dim3(H_/128, MR_/128), blk>>>(x, Wv, MR_, H_, H_, EpiQKV{bv, vp});

    // attention
    const int shmem = 4*17408 + 4*64*(int)sizeof(float);   // 70656 bytes
    cudaFuncSetAttribute(attn_kernel, cudaFuncAttributeMaxDynamicSharedMemorySize, shmem);
    attn_kernel<<<dim3(S_/64, B_*NH_), blk, shmem>>>(mask);

    // O projection + residual, LN1
    gemm_tf32<<<dim3(H_/128, MR_/128), blk>>>(ctxp, Wo, MR_, H_, H_, EpiBiasRes{bo, x, tmpp});
    ln_kernel<<<MR_, 256>>>(tmpp, ln1g, ln1b, x1p);

    // FFN
    gemm_tf32<<<dim3(FF_/128, MR_/128), blk>>>(x1p, W1, MR_, FF_, H_, EpiGelu{b1, ffp});
    gemm_tf32<<<dim3(H_/128, MR_/128), blk>>>(ffp, W2, MR_, H_, FF_, EpiBiasRes{b2, x1p, tmpp});
    ln_kernel<<<MR_, 256>>>(tmpp, ln2g, ln2b, out);
}

// round 5
// speedup vs baseline: 1.9567x; 1.9567x over previous
#include <cuda_runtime.h>
#include <cstdint>
#include <math.h>

// ---------------- problem constants ----------------
#define B_   4
#define S_   2048
#define H_   1024
#define NH_  16
#define HD_  64
#define FF_  4096
#define MR_  (B_*S_)        // 8192 rows

// ---------------- scratch (device globals; no runtime allocation) ----------------
__device__ float g_q  [(size_t)MR_*H_];
__device__ float g_k  [(size_t)MR_*H_];
__device__ float g_v  [(size_t)MR_*H_];
__device__ float g_ctx[(size_t)MR_*H_];
__device__ float g_tmp[(size_t)MR_*H_];
__device__ float g_x1 [(size_t)MR_*H_];
__device__ float g_ff [(size_t)MR_*FF_];

// ---------------- helpers ----------------
__device__ __forceinline__ void cpa16(void* dst, const void* src) {
    uint32_t d = (uint32_t)__cvta_generic_to_shared(dst);
    asm volatile("cp.async.cg.shared.global [%0], [%1], 16;" :: "r"(d), "l"(src));
}
__device__ __forceinline__ void cp_commit() { asm volatile("cp.async.commit_group;"); }
__device__ __forceinline__ void cp_wait0()  { asm volatile("cp.async.wait_group 0;"); }
__device__ __forceinline__ void cp_wait1()  { asm volatile("cp.async.wait_group 1;"); }

// mma.sync tf32: operands are raw fp32 bits (HW truncates mantissa to tf32)
__device__ __forceinline__ void mma8(float* c, const float* a, const float* b) {
    const uint32_t* A = reinterpret_cast<const uint32_t*>(a);
    const uint32_t* Bp = reinterpret_cast<const uint32_t*>(b);
    asm volatile(
        "mma.sync.aligned.m16n8k8.row.col.f32.tf32.tf32.f32 "
        "{%0,%1,%2,%3}, {%4,%5,%6,%7}, {%8,%9}, {%0,%1,%2,%3};"
        : "+f"(c[0]), "+f"(c[1]), "+f"(c[2]), "+f"(c[3])
        : "r"(A[0]), "r"(A[1]), "r"(A[2]), "r"(A[3]), "r"(Bp[0]), "r"(Bp[1]));
}

// ---------------- epilogues ----------------
struct EpiQKV {   // write [B,NH,S,HD] layout, add bias
    const float* bias; float* dst;
    __device__ __forceinline__ void operator()(int r, int c, float v) const {
        int b = r >> 11, s = r & 2047, h = c >> 6, d = c & 63;
        dst[(((size_t)(b*NH_ + h))*S_ + s)*HD_ + d] = v + bias[c];
    }
};
struct EpiBiasRes {   // out = v + bias + residual   (N = H_)
    const float* bias; const float* res; float* dst;
    __device__ __forceinline__ void operator()(int r, int c, float v) const {
        size_t idx = (size_t)r*H_ + c;
        dst[idx] = v + bias[c] + res[idx];
    }
};
struct EpiGelu {      // out = gelu_tanh(v + bias)   (N = FF_)
    const float* bias; float* dst;
    __device__ __forceinline__ void operator()(int r, int c, float v) const {
        float x = v + bias[c];
        float t = tanhf(0.7978845608028654f * (x + 0.044715f * x * x * x));
        dst[(size_t)r*FF_ + c] = 0.5f * x * (1.0f + t);
    }
};

// ---------------- tf32 GEMM: C[M,N] = A[M,K] @ B[K,N] ----------------
// tile 128x128x32, 256 threads = 8 warps (2x4), warp tile 64x32
// double-buffered cp.async, natural smem layouts:
//   As[2][128][36]  (pad 4 -> frag banks grp*4+tig, conflict-free)
//   Bs[2][32][136]  (pad 8 -> frag banks tig*8+grp, conflict-free)
#define AS(buf,r,c) smem[(buf)*4608 + (r)*36 + (c)]
#define BS(buf,r,c) smem[9216 + (buf)*4352 + (r)*136 + (c)]

template <class Epi>
__global__ __launch_bounds__(256, 2) void gemm_tf32(
    const float* __restrict__ A, const float* __restrict__ Bm,
    int M, int N, int K, Epi epi)
{
    extern __shared__ float smem[];

    const int tid  = threadIdx.x;
    const int w    = tid >> 5, lane = tid & 31;
    const int grp  = lane >> 2, tig = lane & 3;
    const int warpM = w >> 2, warpN = w & 3;       // 2 x 4
    const int row0 = blockIdx.y * 128, col0 = blockIdx.x * 128;

    float c[4][4][4];
    #pragma unroll
    for (int i = 0; i < 4; i++)
        #pragma unroll
        for (int j = 0; j < 4; j++)
            #pragma unroll
            for (int l = 0; l < 4; l++) c[i][j][l] = 0.f;

    // chunk decompositions (16B):
    // A tile 128x32: 1024 chunks, row = c>>3, col = (c&7)*4
    // B tile 32x128: 1024 chunks, row = c>>5, col = (c&31)*4
    const int caR[4] = { (tid    )>>3, (tid+256)>>3, (tid+512)>>3, (tid+768)>>3 };
    const int caC = (tid & 7) * 4;
    const int cbR[4] = { (tid    )>>5, (tid+256)>>5, (tid+512)>>5, (tid+768)>>5 };
    const int cbC = (tid & 31) * 4;

    auto load_tile = [&](int kk, int buf) {
        #pragma unroll
        for (int i = 0; i < 4; i++)
            cpa16(&AS(buf, caR[i], caC), A + (size_t)(row0 + caR[i])*K + kk + caC);
        #pragma unroll
        for (int i = 0; i < 4; i++)
            cpa16(&BS(buf, cbR[i], cbC), Bm + (size_t)(kk + cbR[i])*N + col0 + cbC);
        cp_commit();
    };

    const int ntk = K >> 5;
    load_tile(0, 0);

    #pragma unroll 1
    for (int t = 0; t < ntk; t++) {
        const int buf = t & 1;
        if (t + 1 < ntk) { load_tile((t+1) << 5, buf ^ 1); cp_wait1(); }
        else             { cp_wait0(); }
        __syncthreads();

        #pragma unroll
        for (int ks = 0; ks < 32; ks += 8) {
            float a[4][4], b[4][2];
            #pragma unroll
            for (int mt = 0; mt < 4; mt++) {
                int rb = warpM*64 + mt*16 + grp;
                a[mt][0] = AS(buf, rb,   ks+tig);
                a[mt][1] = AS(buf, rb+8, ks+tig);
                a[mt][2] = AS(buf, rb,   ks+tig+4);
                a[mt][3] = AS(buf, rb+8, ks+tig+4);
            }
            #pragma unroll
            for (int nt = 0; nt < 4; nt++) {
                int cb = warpN*32 + nt*8 + grp;
                b[nt][0] = BS(buf, ks+tig,   cb);
                b[nt][1] = BS(buf, ks+tig+4, cb);
            }
            #pragma unroll
            for (int mt = 0; mt < 4; mt++)
                #pragma unroll
                for (int nt = 0; nt < 4; nt++)
                    mma8(c[mt][nt], a[mt], b[nt]);
        }
        __syncthreads();
    }

    #pragma unroll
    for (int mt = 0; mt < 4; mt++) {
        int r = row0 + warpM*64 + mt*16 + grp;
        #pragma unroll
        for (int nt = 0; nt < 4; nt++) {
            int cc = col0 + warpN*32 + nt*8 + tig*2;
            epi(r,     cc,   c[mt][nt][0]);
            epi(r,     cc+1, c[mt][nt][1]);
            epi(r+8,   cc,   c[mt][nt][2]);
            epi(r+8,   cc+1, c[mt][nt][3]);
        }
    }
}

// ---------------- flash attention ----------------
// q-tile 128 / block, 8 warps each own 16 q-rows x all 64 keys.
// Register softmax (quad shfl reductions), shfl-transposed P for PV mma.
// K/V double-buffered cp.async. Natural layouts:
//   Qs[128][68], Ks[2][64][68], Vs[2][64][72], msk[2][64]
#define QS(r,c)      sm[(r)*68 + (c)]
#define KS(buf,r,c)  sm[8704 + (buf)*4352 + (r)*68 + (c)]
#define VS(buf,r,c)  sm[17408 + (buf)*4608 + (r)*72 + (c)]
#define MSK(buf,i)   sm[26624 + (buf)*64 + (i)]
#define ATTN_SMEM (26752*4)

__global__ __launch_bounds__(256, 2) void attn_kernel(const float* __restrict__ mask)
{
    extern __shared__ float sm[];

    const int tid = threadIdx.x, w = tid >> 5, lane = tid & 31;
    const int grp = lane >> 2, tig = lane & 3;
    const int qt = blockIdx.x, bh = blockIdx.y;
    const int b = bh >> 4, h = bh & 15;

    const float* qg = g_q + (size_t)bh * S_ * HD_;
    const float* kg = g_k + (size_t)bh * S_ * HD_;
    const float* vg = g_v + (size_t)bh * S_ * HD_;

    // K/V chunk decomposition: 64x64 tile = 1024 chunks, row=c>>4, col=(c&15)*4
    const int kR[4] = { (tid)>>4, (tid+256)>>4, (tid+512)>>4, (tid+768)>>4 };
    const int kC = (tid & 15) * 4;

    auto load_kv = [&](int kt, int buf) {
        #pragma unroll
        for (int i = 0; i < 4; i++)
            cpa16(&KS(buf, kR[i], kC), kg + (size_t)(kt*64 + kR[i])*HD_ + kC);
        #pragma unroll
        for (int i = 0; i < 4; i++)
            cpa16(&VS(buf, kR[i], kC), vg + (size_t)(kt*64 + kR[i])*HD_ + kC);
        if (tid < 16)
            cpa16(&MSK(buf, tid*4), mask + (size_t)b*S_ + kt*64 + tid*4);
        cp_commit();
    };

    // prologue: Q tile (128x64 = 2048 chunks, 8/thread) + first KV in group 0
    {
        #pragma unroll
        for (int i = 0; i < 8; i++) {
            int cq = tid + i*256;
            int r = cq >> 4, c4 = (cq & 15) * 4;
            cpa16(&QS(r, c4), qg + (size_t)(qt*128 + r)*HD_ + c4);
        }
        load_kv(0, 0);
    }

    float o[8][4];
    #pragma unroll
    for (int i = 0; i < 8; i++)
        #pragma unroll
        for (int j = 0; j < 4; j++) o[i][j] = 0.f;
    float m0 = -1e30f, m1 = -1e30f, l0 = 0.f, l1 = 0.f;

    const float scale = 0.125f;   // 1/sqrt(64)
    const int wq = w * 16;
    const int qbase = lane & ~3;
    const int sA = qbase + (tig >> 1);
    const int sB = qbase + 2 + (tig >> 1);
    const bool odd = tig & 1;

    #pragma unroll 1
    for (int kt = 0; kt < S_/64; kt++) {
        const int buf = kt & 1;
        if (kt + 1 < S_/64) { load_kv(kt+1, buf ^ 1); cp_wait1(); }
        else                { cp_wait0(); }
        __syncthreads();

        // ---- scores = Q @ K^T ----
        float sc[8][4];
        #pragma unroll
        for (int i = 0; i < 8; i++)
            #pragma unroll
            for (int j = 0; j < 4; j++) sc[i][j] = 0.f;

        #pragma unroll
        for (int ks = 0; ks < 64; ks += 8) {
            float a[4];
            a[0] = QS(wq+grp,   ks+tig);
            a[1] = QS(wq+grp+8, ks+tig);
            a[2] = QS(wq+grp,   ks+tig+4);
            a[3] = QS(wq+grp+8, ks+tig+4);
            #pragma unroll
            for (int nt = 0; nt < 8; nt++) {
                float bfr[2];
                bfr[0] = KS(buf, nt*8+grp, ks+tig);
                bfr[1] = KS(buf, nt*8+grp, ks+tig+4);
                mma8(sc[nt], a, bfr);
            }
        }

        // ---- register softmax ----
        float rmax0 = -1e30f, rmax1 = -1e30f;
        #pragma unroll
        for (int nt = 0; nt < 8; nt++) {
            int c0 = nt*8 + tig*2;
            float mk0 = MSK(buf, c0), mk1 = MSK(buf, c0+1);
            sc[nt][0] = sc[nt][0]*scale + mk0;
            sc[nt][1] = sc[nt][1]*scale + mk1;
            sc[nt][2] = sc[nt][2]*scale + mk0;
            sc[nt][3] = sc[nt][3]*scale + mk1;
            rmax0 = fmaxf(rmax0, fmaxf(sc[nt][0], sc[nt][1]));
            rmax1 = fmaxf(rmax1, fmaxf(sc[nt][2], sc[nt][3]));
        }
        rmax0 = fmaxf(rmax0, __shfl_xor_sync(0xffffffffu, rmax0, 1));
        rmax0 = fmaxf(rmax0, __shfl_xor_sync(0xffffffffu, rmax0, 2));
        rmax1 = fmaxf(rmax1, __shfl_xor_sync(0xffffffffu, rmax1, 1));
        rmax1 = fmaxf(rmax1, __shfl_xor_sync(0xffffffffu, rmax1, 2));

        float mn0 = fmaxf(m0, rmax0), mn1 = fmaxf(m1, rmax1);
        float alpha0 = __expf(m0 - mn0), alpha1 = __expf(m1 - mn1);
        m0 = mn0; m1 = mn1;

        float sum0 = 0.f, sum1 = 0.f;
        #pragma unroll
        for (int nt = 0; nt < 8; nt++) {
            sc[nt][0] = __expf(sc[nt][0] - mn0);
            sc[nt][1] = __expf(sc[nt][1] - mn0);
            sc[nt][2] = __expf(sc[nt][2] - mn1);
            sc[nt][3] = __expf(sc[nt][3] - mn1);
            sum0 += sc[nt][0] + sc[nt][1];
            sum1 += sc[nt][2] + sc[nt][3];
        }
        sum0 += __shfl_xor_sync(0xffffffffu, sum0, 1);
        sum0 += __shfl_xor_sync(0xffffffffu, sum0, 2);
        sum1 += __shfl_xor_sync(0xffffffffu, sum1, 1);
        sum1 += __shfl_xor_sync(0xffffffffu, sum1, 2);
        l0 = l0*alpha0 + sum0;
        l1 = l1*alpha1 + sum1;

        #pragma unroll
        for (int nt = 0; nt < 8; nt++) {
            o[nt][0] *= alpha0; o[nt][1] *= alpha0;
            o[nt][2] *= alpha1; o[nt][3] *= alpha1;
        }

        // ---- O += P @ V (P via quad shfl-transpose into A-frag layout) ----
        #pragma unroll
        for (int kk = 0; kk < 8; kk++) {
            float u0 = __shfl_sync(0xffffffffu, sc[kk][0], sA);
            float u1 = __shfl_sync(0xffffffffu, sc[kk][1], sA);
            float u2 = __shfl_sync(0xffffffffu, sc[kk][2], sA);
            float u3 = __shfl_sync(0xffffffffu, sc[kk][3], sA);
            float w0 = __shfl_sync(0xffffffffu, sc[kk][0], sB);
            float w1 = __shfl_sync(0xffffffffu, sc[kk][1], sB);
            float w2 = __shfl_sync(0xffffffffu, sc[kk][2], sB);
            float w3 = __shfl_sync(0xffffffffu, sc[kk][3], sB);
            float a[4];
            a[0] = odd ? u1 : u0;   // P[r0][8kk+tig]
            a[1] = odd ? u3 : u2;   // P[r1][8kk+tig]
            a[2] = odd ? w1 : w0;   // P[r0][8kk+tig+4]
            a[3] = odd ? w3 : w2;   // P[r1][8kk+tig+4]
            #pragma unroll
            for (int nt = 0; nt < 8; nt++) {
                float bfr[2];
                bfr[0] = VS(buf, kk*8+tig,   nt*8+grp);
                bfr[1] = VS(buf, kk*8+tig+4, nt*8+grp);
                mma8(o[nt], a, bfr);
            }
        }
        __syncthreads();
    }

    // ---- epilogue: O / l -> ctx [B,S,H] ----
    float inv0 = 1.f / l0, inv1 = 1.f / l1;
    int q0 = qt*128 + wq + grp, q1 = q0 + 8;
    #pragma unroll
    for (int nt = 0; nt < 8; nt++) {
        int d0 = nt*8 + tig*2;
        float2 v0 = make_float2(o[nt][0]*inv0, o[nt][1]*inv0);
        float2 v1 = make_float2(o[nt][2]*inv1, o[nt][3]*inv1);
        *reinterpret_cast<float2*>(g_ctx + ((size_t)(b*S_ + q0))*H_ + h*HD_ + d0) = v0;
        *reinterpret_cast<float2*>(g_ctx + ((size_t)(b*S_ + q1))*H_ + h*HD_ + d0) = v1;
    }
}

// ---------------- layernorm: one block per row ----------------
__global__ __launch_bounds__(256) void ln_kernel(
    const float* __restrict__ in, const float* __restrict__ g,
    const float* __restrict__ bb, float* __restrict__ out)
{
    __shared__ float red[18];
    const int row = blockIdx.x, tid = threadIdx.x;
    const float4 x = reinterpret_cast<const float4*>(in + (size_t)row*H_)[tid];
    float s  = x.x + x.y + x.z + x.w;
    float sq = x.x*x.x + x.y*x.y + x.z*x.z + x.w*x.w;
    #pragma unroll
    for (int off = 16; off > 0; off >>= 1) {
        s  += __shfl_xor_sync(0xffffffffu, s,  off);
        sq += __shfl_xor_sync(0xffffffffu, sq, off);
    }
    if ((tid & 31) == 0) { red[tid>>5] = s; red[8 + (tid>>5)] = sq; }
    __syncthreads();
    if (tid == 0) {
        float a = 0.f, c2 = 0.f;
        #pragma unroll
        for (int i = 0; i < 8; i++) { a += red[i]; c2 += red[8+i]; }
        red[16] = a; red[17] = c2;
    }
    __syncthreads();
    float mu  = red[16] * (1.f/1024.f);
    float var = red[17] * (1.f/1024.f) - mu*mu;
    float inv = rsqrtf(var + 1e-12f);
    float4 gv = reinterpret_cast<const float4*>(g)[tid];
    float4 bv = reinterpret_cast<const float4*>(bb)[tid];
    float4 o4;
    o4.x = (x.x - mu)*inv*gv.x + bv.x;
    o4.y = (x.y - mu)*inv*gv.y + bv.y;
    o4.z = (x.z - mu)*inv*gv.z + bv.z;
    o4.w = (x.w - mu)*inv*gv.w + bv.w;
    reinterpret_cast<float4*>(out + (size_t)row*H_)[tid] = o4;
}

// ---------------- launch ----------------
#define GEMM_SMEM (17920*4)

extern "C" void kernel_launch(void* const* d_in, const int* in_sizes, int n_in,
                              void* d_out, int out_size)
{
    (void)in_sizes; (void)n_in; (void)out_size;
    const float* x    = (const float*)d_in[0];
    const float* mask = (const float*)d_in[1];
    const float* Wq   = (const float*)d_in[2];
    const float* bq   = (const float*)d_in[3];
    const float* Wk   = (const float*)d_in[4];
    const float* bk   = (const float*)d_in[5];
    const float* Wv   = (const float*)d_in[6];
    const float* bv   = (const float*)d_in[7];
    const float* Wo   = (const float*)d_in[8];
    const float* bo   = (const float*)d_in[9];
    const float* ln1g = (const float*)d_in[10];
    const float* ln1b = (const float*)d_in[11];
    const float* W1   = (const float*)d_in[12];
    const float* b1   = (const float*)d_in[13];
    const float* W2   = (const float*)d_in[14];
    const float* b2   = (const float*)d_in[15];
    const float* ln2g = (const float*)d_in[16];
    const float* ln2b = (const float*)d_in[17];
    float* out = (float*)d_out;

    float *qp, *kp, *vp, *ctxp, *tmpp, *x1p, *ffp;
    cudaGetSymbolAddress((void**)&qp,   g_q);
    cudaGetSymbolAddress((void**)&kp,   g_k);
    cudaGetSymbolAddress((void**)&vp,   g_v);
    cudaGetSymbolAddress((void**)&ctxp, g_ctx);
    cudaGetSymbolAddress((void**)&tmpp, g_tmp);
    cudaGetSymbolAddress((void**)&x1p,  g_x1);
    cudaGetSymbolAddress((void**)&ffp,  g_ff);

    // set every call (idempotent; no static guards per harness rules)
    cudaFuncSetAttribute(gemm_tf32<EpiQKV>,     cudaFuncAttributeMaxDynamicSharedMemorySize, GEMM_SMEM);
    cudaFuncSetAttribute(gemm_tf32<EpiBiasRes>, cudaFuncAttributeMaxDynamicSharedMemorySize, GEMM_SMEM);
    cudaFuncSetAttribute(gemm_tf32<EpiGelu>,    cudaFuncAttributeMaxDynamicSharedMemorySize, GEMM_SMEM);
    cudaFuncSetAttribute(attn_kernel,           cudaFuncAttributeMaxDynamicSharedMemorySize, ATTN_SMEM);

    dim3 blk(256);

    // QKV projections
    gemm_tf32<<<dim3(H_/128, MR_/128), blk, GEMM_SMEM>>>(x, Wq, MR_, H_, H_, EpiQKV{bq, qp});
    gemm_tf32<<<dim3(H_/128, MR_/128), blk, GEMM_SMEM>>>(x, Wk, MR_, H_, H_, EpiQKV{bk, kp});
    gemm_tf32<<<dim3(H_/128, MR_/128), blk, GEMM_SMEM>>>(x, Wv, MR_, H_, H_, EpiQKV{bv, vp});

    // attention
    attn_kernel<<<dim3(S_/128, B_*NH_), blk, ATTN_SMEM>>>(mask);

    // O projection + residual, LN1
    gemm_tf32<<<dim3(H_/128, MR_/128), blk, GEMM_SMEM>>>(ctxp, Wo, MR_, H_, H_, EpiBiasRes{bo, x, tmpp});
    ln_kernel<<<MR_, 256>>>(tmpp, ln1g, ln1b, x1p);

    // FFN
    gemm_tf32<<<dim3(FF_/128, MR_/128), blk, GEMM_SMEM>>>(x1p, W1, MR_, FF_, H_, EpiGelu{b1, ffp});
    gemm_tf32<<<dim3(H_/128, MR_/128), blk, GEMM_SMEM>>>(ffp, W2, MR_, H_, FF_, EpiBiasRes{b2, x1p, tmpp});
    ln_kernel<<<MR_, 256>>>(tmpp, ln2g, ln2b, out);
}